// round 6
// baseline (speedup 1.0000x reference)
#include <cuda_runtime.h>
#include <math.h>
#include <stdint.h>

#define EPSF 1e-6f
#define NBATCH 4096
#define RS 132            // padded row stride (layout [k][row]), mult of 4

// k-major repacked weights (+4 zero-padded rows for unconditional depth-4 prefetch)
__device__ float g_W1c[(114 + 4) * 256];   // [k][out]
__device__ float g_W2c[(256 + 4) * 128];   // [k][out]

// ---------------------------------------------------------------------------
__device__ __forceinline__ float2 ffma2(float2 a, float2 b, float2 c) {
    float2 d;
    asm("fma.rn.f32x2 %0, %1, %2, %3;"
        : "=l"(reinterpret_cast<unsigned long long&>(d))
        : "l"(reinterpret_cast<unsigned long long&>(a)),
          "l"(reinterpret_cast<unsigned long long&>(b)),
          "l"(reinterpret_cast<unsigned long long&>(c)));
    return d;
}

__device__ __forceinline__ float my_sinf(float x) {
    float k = rintf(x * 0.318309886183790672f);
    float r = fmaf(k, -3.14159274101257324f, x);
    r = fmaf(k, 8.742278012618954e-8f, r);
    float r2 = r * r;
    float p = -2.50521083854e-08f;
    p = fmaf(p, r2, 2.75573192239e-06f);
    p = fmaf(p, r2, -1.98412698413e-04f);
    p = fmaf(p, r2, 8.33333333333e-03f);
    p = fmaf(p, r2, -1.66666666667e-01f);
    float s = fmaf(p * r2, r, r);
    int ki = __float2int_rn(k);
    return (ki & 1) ? -s : s;
}

__device__ __forceinline__ float leaky_f(float x) { return x >= 0.f ? x : 0.1f * x; }

// ---------------------------------------------------------------------------
// repack W1 [256,114] -> W1c [114+4,256]; W2 [128,256] -> W2c [256+4,128]
// ---------------------------------------------------------------------------
__global__ void repack_kernel(const float* __restrict__ W1,
                              const float* __restrict__ W2)
{
    int idx = blockIdx.x * 256 + threadIdx.x;
    if (idx < (114 + 4) * 256) {
        int k = idx >> 8, o = idx & 255;
        g_W1c[idx] = (k < 114) ? W1[o * 114 + k] : 0.f;
    }
    if (idx < (256 + 4) * 128) {
        int k = idx >> 7, o = idx & 127;
        g_W2c[idx] = (k < 256) ? W2[o * 256 + k] : 0.f;
    }
}

// ---------------------------------------------------------------------------
// feature helpers (aug block layout: data 0,1 | sin 2..18 | sqr 19,20 |
// cub 21,22 | exp 23,24 | inv 25,26 | 1/sin 27..43 | 1/sqr 44,45 |
// 1/cub 46,47 | 1/exp 48,49)
// ---------------------------------------------------------------------------
__device__ __forceinline__ void aug_poly(float* __restrict__ Acol, int base,
                                         float dx, float dy)
{
    Acol[(base+0)*RS] = dx;
    Acol[(base+1)*RS] = dy;
    float sqx = dx*dx + EPSF, sqy = dy*dy + EPSF;
    float cbx = dx*dx*dx + EPSF, cby = dy*dy*dy + EPSF;
    float exx = expf(dx) + EPSF, exy = expf(dy) + EPSF;
    Acol[(base+19)*RS] = sqx;  Acol[(base+20)*RS] = sqy;
    Acol[(base+21)*RS] = cbx;  Acol[(base+22)*RS] = cby;
    Acol[(base+23)*RS] = exx;  Acol[(base+24)*RS] = exy;
    Acol[(base+25)*RS] = 1.0f / (dx + EPSF);
    Acol[(base+26)*RS] = 1.0f / (dy + EPSF);
    Acol[(base+44)*RS] = 1.0f / sqx;  Acol[(base+45)*RS] = 1.0f / sqy;
    Acol[(base+46)*RS] = 1.0f / cbx;  Acol[(base+47)*RS] = 1.0f / cby;
    Acol[(base+48)*RS] = 1.0f / exx;  Acol[(base+49)*RS] = 1.0f / exy;
}

__device__ __forceinline__ void aug_sin(float* __restrict__ Acol, int base,
                                        float dx, float dy,
                                        const float* __restrict__ W_s1,
                                        const float* __restrict__ b_s1,
                                        int j0, int j1)
{
    #pragma unroll 1
    for (int j = j0; j < j1; j++) {
        float arg = fmaf(dx, __ldg(W_s1 + 2*j),
                    fmaf(dy, __ldg(W_s1 + 2*j + 1), __ldg(b_s1 + j)));
        float s = my_sinf(arg) + EPSF;
        Acol[(base+2+j)*RS]  = s;
        Acol[(base+27+j)*RS] = 1.0f / s;
    }
}

// ---------------------------------------------------------------------------
// GEMM tile: 16 rows x TO outs per thread, depth-4 weight prefetch.
// rt in [0,8): rows {4rt+32j | j<4, 4 consecutive each}; ot: outs ot*TO..+TO-1.
// Weights Wc[k][LDWC] k-major; 1 vector LDG per k per thread.
// ---------------------------------------------------------------------------
template<int TO>
__device__ __forceinline__ void loadw(float* w, const float* p) {
    if constexpr (TO == 4) {
        float4 t = __ldg(reinterpret_cast<const float4*>(p));
        w[0] = t.x; w[1] = t.y; w[2] = t.z; w[3] = t.w;
    } else {
        float2 t = __ldg(reinterpret_cast<const float2*>(p));
        w[0] = t.x; w[1] = t.y;
    }
}

template<int K, int TO, int LDWC>
__device__ __forceinline__ void gemm2(const float* __restrict__ At,
                                      const float* __restrict__ Wc,
                                      const float* __restrict__ bg,
                                      float* __restrict__ Ct,
                                      int rt, int ot)
{
    float2 acc[4][2][TO];
    #pragma unroll
    for (int i = 0; i < TO; i++) {
        float bo = __ldg(bg + ot*TO + i);
        #pragma unroll
        for (int j = 0; j < 4; j++) {
            acc[j][0][i] = make_float2(bo, bo);
            acc[j][1][i] = make_float2(bo, bo);
        }
    }
    const float* xb = At + 4*rt;
    const float* wp = Wc + ot*TO;

    float w0[TO], w1[TO], w2[TO], w3[TO];
    loadw<TO>(w0, wp + 0*LDWC);
    loadw<TO>(w1, wp + 1*LDWC);
    loadw<TO>(w2, wp + 2*LDWC);
    loadw<TO>(w3, wp + 3*LDWC);

    #pragma unroll 4
    for (int k = 0; k < K; k++) {
        float4 x0 = *reinterpret_cast<const float4*>(xb + k*RS);
        float4 x1 = *reinterpret_cast<const float4*>(xb + k*RS + 32);
        float4 x2 = *reinterpret_cast<const float4*>(xb + k*RS + 64);
        float4 x3 = *reinterpret_cast<const float4*>(xb + k*RS + 96);
        float wn[TO];
        loadw<TO>(wn, wp + (k + 4)*LDWC);   // unconditional (padded)

        #pragma unroll
        for (int i = 0; i < TO; i++) {
            float2 ws = make_float2(w0[i], w0[i]);
            acc[0][0][i] = ffma2(make_float2(x0.x, x0.y), ws, acc[0][0][i]);
            acc[0][1][i] = ffma2(make_float2(x0.z, x0.w), ws, acc[0][1][i]);
            acc[1][0][i] = ffma2(make_float2(x1.x, x1.y), ws, acc[1][0][i]);
            acc[1][1][i] = ffma2(make_float2(x1.z, x1.w), ws, acc[1][1][i]);
            acc[2][0][i] = ffma2(make_float2(x2.x, x2.y), ws, acc[2][0][i]);
            acc[2][1][i] = ffma2(make_float2(x2.z, x2.w), ws, acc[2][1][i]);
            acc[3][0][i] = ffma2(make_float2(x3.x, x3.y), ws, acc[3][0][i]);
            acc[3][1][i] = ffma2(make_float2(x3.z, x3.w), ws, acc[3][1][i]);
        }
        // rotate (renamed away by unroll)
        #pragma unroll
        for (int i = 0; i < TO; i++) {
            w0[i] = w1[i]; w1[i] = w2[i]; w2[i] = w3[i]; w3[i] = wn[i];
        }
    }

    // epilogue: leaky + STS.128 per (out, row-chunk)
    #pragma unroll
    for (int i = 0; i < TO; i++) {
        #pragma unroll
        for (int j = 0; j < 4; j++) {
            float4 v;
            v.x = leaky_f(acc[j][0][i].x);
            v.y = leaky_f(acc[j][0][i].y);
            v.z = leaky_f(acc[j][1][i].x);
            v.w = leaky_f(acc[j][1][i].y);
            *reinterpret_cast<float4*>(Ct + (ot*TO + i)*RS + 4*rt + 32*j) = v;
        }
    }
}

// smem layout
#define SM_R0   (128*RS)
#define SM_R1   (256*RS)
#define SM_EN   (SM_R0 + SM_R1)
#define SM_LG   (SM_EN + 256)
#define SM_TOT  (SM_LG + 128)

#define EN_BLOCKS (NBATCH/2)

__global__ void __launch_bounds__(512, 1)
fused_kernel(const float* __restrict__ ego_y,
             const float* __restrict__ Pn,  const float* __restrict__ Pego,
             const float* __restrict__ Vn,  const float* __restrict__ Vego,
             const float* __restrict__ Cn,
             const float* __restrict__ W_sel, const float* __restrict__ b_sel,
             const float* __restrict__ W_s0,  const float* __restrict__ b_s0,
             const float* __restrict__ W_map, const float* __restrict__ b_map,
             const float* __restrict__ W_efc, const float* __restrict__ b_efc,
             const float* __restrict__ W_s1, const float* __restrict__ b_s1,
             const float* __restrict__ b1,
             const float* __restrict__ b2,
             const float* __restrict__ W3,  const float* __restrict__ b3,
             const float* __restrict__ Ww,  const float* __restrict__ bw,
             float* __restrict__ out)
{
    extern __shared__ float sm[];
    int tid = threadIdx.x;
    int blk = blockIdx.x;

    // =======================================================================
    // Er head blocks
    // =======================================================================
    if (blk >= EN_BLOCKS) {
        if (tid < 256) {
            int b = (blk - EN_BLOCKS) * 256 + tid;
            float ey = ego_y[b];
            float dy[4] = { 13.55f - ey, 17.45f - ey, 21.12f - ey, 24.91f - ey };

            float z[4];
            #pragma unroll
            for (int o = 0; o < 4; o++) {
                float a = __ldg(b_sel + o);
                #pragma unroll
                for (int i = 0; i < 4; i++) a = fmaf(dy[i], __ldg(W_sel + o*4+i), a);
                z[o] = a;
            }
            float m = fmaxf(fmaxf(z[0], z[1]), fmaxf(z[2], z[3]));
            float e[4], ssum = 0.f;
            #pragma unroll
            for (int i = 0; i < 4; i++) { e[i] = expf(z[i] - m); ssum += e[i]; }
            float x[4];
            #pragma unroll
            for (int i = 0; i < 4; i++) x[i] = (e[i] / ssum) * dy[i];

            float f[48];
            #pragma unroll
            for (int i = 0; i < 4; i++) f[i] = x[i];
            #pragma unroll
            for (int j = 0; j < 8; j++) {
                float arg = __ldg(b_s0 + j);
                #pragma unroll
                for (int i = 0; i < 4; i++) arg = fmaf(x[i], __ldg(W_s0 + j*4+i), arg);
                float s = my_sinf(arg) + EPSF;
                f[4 + j] = s;
                f[28 + j] = 1.0f / s;
            }
            #pragma unroll
            for (int i = 0; i < 4; i++) {
                float sq = x[i]*x[i] + EPSF;
                float cb = x[i]*x[i]*x[i] + EPSF;
                float ex = expf(x[i]) + EPSF;
                f[12+i] = sq;           f[36+i] = 1.0f / sq;
                f[16+i] = cb;           f[40+i] = 1.0f / cb;
                f[20+i] = ex;           f[44+i] = 1.0f / ex;
                f[24+i] = 1.0f / (x[i] + EPSF);
            }
            float y[8];
            #pragma unroll
            for (int o = 0; o < 8; o++) {
                float a = __ldg(b_map + o);
                #pragma unroll
                for (int k = 0; k < 48; k++) a = fmaf(f[k], __ldg(W_map + o*48+k), a);
                y[o] = leaky_f(a);
            }
            float r0 = __ldg(b_efc), r1 = __ldg(b_efc + 1);
            #pragma unroll
            for (int k = 0; k < 8; k++) {
                r0 = fmaf(y[k], __ldg(W_efc + k),     r0);
                r1 = fmaf(y[k], __ldg(W_efc + 8 + k), r1);
            }
            out[b*4 + 0] = r0;
            out[b*4 + 1] = r1;
        }
        return;
    }

    // =======================================================================
    // En blocks: 128 rows (2 batches x 64 neighbors)
    // =======================================================================
    float* At  = sm;              // features (transposed), later h2_T
    float* h1T = sm + SM_R0;      // h1, then layer3 partial scratch
    float* enb = sm + SM_EN;
    float* lgb = sm + SM_LG;

    // ---- phase 0: features, 4 threads per row ----
    {
        int r = tid >> 2;
        int part = tid & 3;
        int b = blk*2 + (r >> 6);
        int n = r & 63;
        int idx2 = (b*64 + n) * 2;
        float* Acol = At + r;
        if (part < 2) {
            float pex = Pego[b*2], pey = Pego[b*2+1];
            float pnx = Pn[idx2],  pny = Pn[idx2+1];
            float dx = pnx - pex,  dy = pny - pey;
            if (part == 0) {
                Acol[0*RS] = pex;  Acol[1*RS] = pey;
                Acol[2*RS] = pnx;  Acol[3*RS] = pny;
                Acol[4*RS] = dx;   Acol[5*RS] = dy;
                Acol[112*RS] = Cn[idx2];
                Acol[113*RS] = Cn[idx2+1];
                aug_poly(Acol, 6, dx, dy);
                aug_sin(Acol, 6, dx, dy, W_s1, b_s1, 0, 9);
            } else {
                aug_sin(Acol, 6, dx, dy, W_s1, b_s1, 9, 17);
            }
        } else {
            float vex = Vego[b*2], vey = Vego[b*2+1];
            float vnx = Vn[idx2],  vny = Vn[idx2+1];
            float dx = vnx - vex,  dy = vny - vey;
            if (part == 2) {
                Acol[56*RS] = vex;  Acol[57*RS] = vey;
                Acol[58*RS] = vnx;  Acol[59*RS] = vny;
                Acol[60*RS] = dx;   Acol[61*RS] = dy;
                aug_poly(Acol, 62, dx, dy);
                aug_sin(Acol, 62, dx, dy, W_s1, b_s1, 0, 9);
            } else {
                aug_sin(Acol, 62, dx, dy, W_s1, b_s1, 9, 17);
            }
        }
    }
    __syncthreads();

    int rt = tid & 7;      // 8 row-groups (16 rows each)
    int ot = tid >> 3;     // 64 out-groups

    // ---- layer1: [128,114] -> [128,256], leaky (TO=4) ----
    gemm2<114, 4, 256>(At, g_W1c, b1, h1T, rt, ot);
    __syncthreads();

    // ---- layer2: [128,256] -> [128,128], leaky (TO=2) ----
    gemm2<256, 2, 128>(h1T, g_W2c, b2, At, rt, ot);
    __syncthreads();

    // ---- layer3: all 512 threads (4 k-segments x 128 rows) ----
    {
        int seg = tid >> 7;
        int r   = tid & 127;
        int k0  = seg * 32;
        float a0 = 0.f, a1 = 0.f;
        #pragma unroll 8
        for (int k = k0; k < k0 + 32; k++) {
            float h = At[k*RS + r];
            a0 = fmaf(h, __ldg(W3 + k),       a0);
            a1 = fmaf(h, __ldg(W3 + 128 + k), a1);
        }
        h1T[(seg*128 + r)*2]     = a0;
        h1T[(seg*128 + r)*2 + 1] = a1;
    }
    __syncthreads();

    // ---- layer3 reduce + logits ----
    if (tid < 128) {
        int r = tid;
        float a0 = __ldg(b3), a1 = __ldg(b3 + 1);
        #pragma unroll
        for (int seg = 0; seg < 4; seg++) {
            a0 += h1T[(seg*128 + r)*2];
            a1 += h1T[(seg*128 + r)*2 + 1];
        }
        enb[r*2]   = a0;
        enb[r*2+1] = a1;
        int b = blk*2 + (r >> 6);
        int n = r & 63;
        int idx2 = (b*64 + n) * 2;
        float pnx = Pn[idx2], pny = Pn[idx2+1];
        float dx = pnx - Pego[b*2], dy = pny - Pego[b*2+1];
        float lg = __ldg(bw);
        lg = fmaf(__ldg(Ww+0), a0,  lg);
        lg = fmaf(__ldg(Ww+1), a1,  lg);
        lg = fmaf(__ldg(Ww+2), pnx, lg);
        lg = fmaf(__ldg(Ww+3), pny, lg);
        lg = fmaf(__ldg(Ww+4), dx,  lg);
        lg = fmaf(__ldg(Ww+5), dy,  lg);
        lgb[r] = lg;
    }
    __syncthreads();

    // ---- softmax over 64 neighbors + weighted sum ----
    if (tid < 64) {
        int w = tid >> 5, l = tid & 31;
        int base = w * 64;
        float v0 = lgb[base + l], v1 = lgb[base + 32 + l];
        float m = fmaxf(v0, v1);
        #pragma unroll
        for (int off = 16; off; off >>= 1)
            m = fmaxf(m, __shfl_xor_sync(0xffffffffu, m, off));
        float e0 = expf(v0 - m), e1 = expf(v1 - m);
        float s  = e0 + e1;
        float n0 = e0 * enb[(base+l)*2]     + e1 * enb[(base+32+l)*2];
        float n1 = e0 * enb[(base+l)*2 + 1] + e1 * enb[(base+32+l)*2 + 1];
        #pragma unroll
        for (int off = 16; off; off >>= 1) {
            s  += __shfl_xor_sync(0xffffffffu, s,  off);
            n0 += __shfl_xor_sync(0xffffffffu, n0, off);
            n1 += __shfl_xor_sync(0xffffffffu, n1, off);
        }
        if (l == 0) {
            int b = blk*2 + w;
            out[b*4 + 2] = n0 / s;
            out[b*4 + 3] = n1 / s;
        }
    }
}

// ---------------------------------------------------------------------------
extern "C" void kernel_launch(void* const* d_in, const int* in_sizes, int n_in,
                              void* d_out, int out_size)
{
    const float* ego_y = (const float*)d_in[0];
    const float* Pn    = (const float*)d_in[1];
    const float* Pego  = (const float*)d_in[2];
    const float* Vn    = (const float*)d_in[3];
    const float* Vego  = (const float*)d_in[4];
    const float* Cn    = (const float*)d_in[5];
    const float* W_sel = (const float*)d_in[6];
    const float* b_sel = (const float*)d_in[7];
    const float* W_s0  = (const float*)d_in[8];
    const float* b_s0  = (const float*)d_in[9];
    const float* W_map = (const float*)d_in[10];
    const float* b_map = (const float*)d_in[11];
    const float* W_efc = (const float*)d_in[12];
    const float* b_efc = (const float*)d_in[13];
    const float* W_s1  = (const float*)d_in[14];
    const float* b_s1  = (const float*)d_in[15];
    const float* W1    = (const float*)d_in[16];
    const float* b1    = (const float*)d_in[17];
    const float* W2    = (const float*)d_in[18];
    const float* b2    = (const float*)d_in[19];
    const float* W3    = (const float*)d_in[20];
    const float* b3    = (const float*)d_in[21];
    const float* Ww    = (const float*)d_in[22];
    const float* bw    = (const float*)d_in[23];
    float* out = (float*)d_out;

    size_t smem_bytes = (size_t)SM_TOT * sizeof(float);
    cudaFuncSetAttribute(fused_kernel, cudaFuncAttributeMaxDynamicSharedMemorySize,
                         (int)smem_bytes);

    repack_kernel<<<130, 256>>>(W1, W2);
    fused_kernel<<<EN_BLOCKS + 16, 512, smem_bytes>>>(
        ego_y, Pn, Pego, Vn, Vego, Cn,
        W_sel, b_sel, W_s0, b_s0, W_map, b_map, W_efc, b_efc,
        W_s1, b_s1, b1, b2, W3, b3, Ww, bw, out);
}

// round 7
// speedup vs baseline: 1.2002x; 1.2002x over previous
#include <cuda_runtime.h>
#include <math.h>
#include <stdint.h>

#define EPSF 1e-6f
#define NBATCH 4096
#define RS 132            // padded row stride (layout [k][row])

// k-major repacked weights; W1 padded to 120 k-rows (zeros) for exact 8-chunks
__device__ float g_W1c[120 * 256];   // [k][out]
__device__ float g_W2c[256 * 128];   // [k][out]

// ---------------------------------------------------------------------------
__device__ __forceinline__ float2 ffma2(float2 a, float2 b, float2 c) {
    float2 d;
    asm("fma.rn.f32x2 %0, %1, %2, %3;"
        : "=l"(reinterpret_cast<unsigned long long&>(d))
        : "l"(reinterpret_cast<unsigned long long&>(a)),
          "l"(reinterpret_cast<unsigned long long&>(b)),
          "l"(reinterpret_cast<unsigned long long&>(c)));
    return d;
}

__device__ __forceinline__ float my_sinf(float x) {
    float k = rintf(x * 0.318309886183790672f);
    float r = fmaf(k, -3.14159274101257324f, x);
    r = fmaf(k, 8.742278012618954e-8f, r);
    float r2 = r * r;
    float p = -2.50521083854e-08f;
    p = fmaf(p, r2, 2.75573192239e-06f);
    p = fmaf(p, r2, -1.98412698413e-04f);
    p = fmaf(p, r2, 8.33333333333e-03f);
    p = fmaf(p, r2, -1.66666666667e-01f);
    float s = fmaf(p * r2, r, r);
    int ki = __float2int_rn(k);
    return (ki & 1) ? -s : s;
}

__device__ __forceinline__ float leaky_f(float x) { return x >= 0.f ? x : 0.1f * x; }

// ---------------------------------------------------------------------------
// repack W1 [256,114] -> W1c [120,256] (rows 114-119 zero);
// W2 [128,256] -> W2c [256,128]
// ---------------------------------------------------------------------------
__global__ void repack_kernel(const float* __restrict__ W1,
                              const float* __restrict__ W2)
{
    int idx = blockIdx.x * 256 + threadIdx.x;
    if (idx < 120 * 256) {
        int k = idx >> 8, o = idx & 255;
        g_W1c[idx] = (k < 114) ? W1[o * 114 + k] : 0.f;
    }
    if (idx < 256 * 128) {
        int k = idx >> 7, o = idx & 127;
        g_W2c[idx] = W2[o * 256 + k];
    }
}

// ---------------------------------------------------------------------------
// feature helpers
// ---------------------------------------------------------------------------
__device__ __forceinline__ void aug_poly(float* __restrict__ Acol, int base,
                                         float dx, float dy)
{
    Acol[(base+0)*RS] = dx;
    Acol[(base+1)*RS] = dy;
    float sqx = dx*dx + EPSF, sqy = dy*dy + EPSF;
    float cbx = dx*dx*dx + EPSF, cby = dy*dy*dy + EPSF;
    float exx = expf(dx) + EPSF, exy = expf(dy) + EPSF;
    Acol[(base+19)*RS] = sqx;  Acol[(base+20)*RS] = sqy;
    Acol[(base+21)*RS] = cbx;  Acol[(base+22)*RS] = cby;
    Acol[(base+23)*RS] = exx;  Acol[(base+24)*RS] = exy;
    Acol[(base+25)*RS] = 1.0f / (dx + EPSF);
    Acol[(base+26)*RS] = 1.0f / (dy + EPSF);
    Acol[(base+44)*RS] = 1.0f / sqx;  Acol[(base+45)*RS] = 1.0f / sqy;
    Acol[(base+46)*RS] = 1.0f / cbx;  Acol[(base+47)*RS] = 1.0f / cby;
    Acol[(base+48)*RS] = 1.0f / exx;  Acol[(base+49)*RS] = 1.0f / exy;
}

__device__ __forceinline__ void aug_sin(float* __restrict__ Acol, int base,
                                        float dx, float dy,
                                        const float* __restrict__ W_s1,
                                        const float* __restrict__ b_s1,
                                        int j0, int j1)
{
    #pragma unroll 1
    for (int j = j0; j < j1; j++) {
        float arg = fmaf(dx, __ldg(W_s1 + 2*j),
                    fmaf(dy, __ldg(W_s1 + 2*j + 1), __ldg(b_s1 + j)));
        float s = my_sinf(arg) + EPSF;
        Acol[(base+2+j)*RS]  = s;
        Acol[(base+27+j)*RS] = 1.0f / s;
    }
}

// ---------------------------------------------------------------------------
// Staged GEMM: weights double-buffered in smem (chunk = 2048 floats = CH k-rows).
// Thread: rt = tid&31 owns rows 4rt..4rt+3 (1 LDS.128/k); ot = tid>>5 owns
// outs ot*TO..+TO-1 (w via broadcast LDS from staged chunk).
// KP must be NC*CH; pad rows of Wg must be zero (x rows may be garbage*0).
// ---------------------------------------------------------------------------
template<int KP, int TO, int CH, int LDWC>
__device__ __forceinline__ void gemm_staged(const float* __restrict__ At,
                                            const float* __restrict__ Wg,
                                            const float* __restrict__ bg,
                                            float* __restrict__ Ct,
                                            float* __restrict__ wbuf,
                                            int rt, int ot, int tid)
{
    constexpr int NC  = KP / CH;
    constexpr int CHW = CH * LDWC;          // 2048 floats per chunk
    float2 acc[2][TO];
    #pragma unroll
    for (int i = 0; i < TO; i++) {
        float bo = __ldg(bg + ot*TO + i);
        acc[0][i] = make_float2(bo, bo);
        acc[1][i] = make_float2(bo, bo);
    }
    const float* xb = At + 4*rt;

    // stage chunk 0
    {
        float4 st = __ldg(reinterpret_cast<const float4*>(Wg) + tid);
        *(reinterpret_cast<float4*>(wbuf) + tid) = st;
    }
    __syncthreads();

    #pragma unroll 1
    for (int c = 0; c < NC; c++) {
        int cn = (c + 1 < NC) ? c + 1 : NC - 1;
        float4 nx = __ldg(reinterpret_cast<const float4*>(Wg + cn*CHW) + tid);

        const float* wb = wbuf + (c & 1)*CHW + ot*TO;
        const float* xk = xb + (c*CH)*RS;

        #pragma unroll
        for (int k = 0; k < CH; k++) {
            float4 xv = *reinterpret_cast<const float4*>(xk + k*RS);
            float w[TO];
            #pragma unroll
            for (int i = 0; i < TO/4; i++) {
                float4 t = *reinterpret_cast<const float4*>(wb + k*LDWC + 4*i);
                w[4*i+0] = t.x; w[4*i+1] = t.y; w[4*i+2] = t.z; w[4*i+3] = t.w;
            }
            float2 p0 = make_float2(xv.x, xv.y);
            float2 p1 = make_float2(xv.z, xv.w);
            #pragma unroll
            for (int i = 0; i < TO; i++) {
                float2 ws = make_float2(w[i], w[i]);
                acc[0][i] = ffma2(p0, ws, acc[0][i]);
                acc[1][i] = ffma2(p1, ws, acc[1][i]);
            }
        }

        // store next chunk (hidden behind compute), then hand off
        *(reinterpret_cast<float4*>(wbuf + ((c + 1) & 1)*CHW) + tid) = nx;
        __syncthreads();
    }

    // epilogue: leaky + 1 STS.128 per out (warp lanes contiguous -> conflict-free)
    #pragma unroll
    for (int i = 0; i < TO; i++) {
        float4 v;
        v.x = leaky_f(acc[0][i].x);
        v.y = leaky_f(acc[0][i].y);
        v.z = leaky_f(acc[1][i].x);
        v.w = leaky_f(acc[1][i].y);
        *reinterpret_cast<float4*>(Ct + (ot*TO + i)*RS + 4*rt) = v;
    }
}

// smem layout (floats)
#define SM_R0   (128*RS)
#define SM_R1   (256*RS)
#define SM_WB   (SM_R0 + SM_R1)
#define SM_EN   (SM_WB + 4096)
#define SM_LG   (SM_EN + 256)
#define SM_TOT  (SM_LG + 128)

#define EN_BLOCKS (NBATCH/2)

__global__ void __launch_bounds__(512, 1)
fused_kernel(const float* __restrict__ ego_y,
             const float* __restrict__ Pn,  const float* __restrict__ Pego,
             const float* __restrict__ Vn,  const float* __restrict__ Vego,
             const float* __restrict__ Cn,
             const float* __restrict__ W_sel, const float* __restrict__ b_sel,
             const float* __restrict__ W_s0,  const float* __restrict__ b_s0,
             const float* __restrict__ W_map, const float* __restrict__ b_map,
             const float* __restrict__ W_efc, const float* __restrict__ b_efc,
             const float* __restrict__ W_s1, const float* __restrict__ b_s1,
             const float* __restrict__ b1,
             const float* __restrict__ b2,
             const float* __restrict__ W3,  const float* __restrict__ b3,
             const float* __restrict__ Ww,  const float* __restrict__ bw,
             float* __restrict__ out)
{
    extern __shared__ float sm[];
    int tid = threadIdx.x;
    int blk = blockIdx.x;

    // =======================================================================
    // Er head blocks
    // =======================================================================
    if (blk >= EN_BLOCKS) {
        if (tid < 256) {
            int b = (blk - EN_BLOCKS) * 256 + tid;
            float ey = ego_y[b];
            float dy[4] = { 13.55f - ey, 17.45f - ey, 21.12f - ey, 24.91f - ey };

            float z[4];
            #pragma unroll
            for (int o = 0; o < 4; o++) {
                float a = __ldg(b_sel + o);
                #pragma unroll
                for (int i = 0; i < 4; i++) a = fmaf(dy[i], __ldg(W_sel + o*4+i), a);
                z[o] = a;
            }
            float m = fmaxf(fmaxf(z[0], z[1]), fmaxf(z[2], z[3]));
            float e[4], ssum = 0.f;
            #pragma unroll
            for (int i = 0; i < 4; i++) { e[i] = expf(z[i] - m); ssum += e[i]; }
            float x[4];
            #pragma unroll
            for (int i = 0; i < 4; i++) x[i] = (e[i] / ssum) * dy[i];

            float f[48];
            #pragma unroll
            for (int i = 0; i < 4; i++) f[i] = x[i];
            #pragma unroll
            for (int j = 0; j < 8; j++) {
                float arg = __ldg(b_s0 + j);
                #pragma unroll
                for (int i = 0; i < 4; i++) arg = fmaf(x[i], __ldg(W_s0 + j*4+i), arg);
                float s = my_sinf(arg) + EPSF;
                f[4 + j] = s;
                f[28 + j] = 1.0f / s;
            }
            #pragma unroll
            for (int i = 0; i < 4; i++) {
                float sq = x[i]*x[i] + EPSF;
                float cb = x[i]*x[i]*x[i] + EPSF;
                float ex = expf(x[i]) + EPSF;
                f[12+i] = sq;           f[36+i] = 1.0f / sq;
                f[16+i] = cb;           f[40+i] = 1.0f / cb;
                f[20+i] = ex;           f[44+i] = 1.0f / ex;
                f[24+i] = 1.0f / (x[i] + EPSF);
            }
            float y[8];
            #pragma unroll
            for (int o = 0; o < 8; o++) {
                float a = __ldg(b_map + o);
                #pragma unroll
                for (int k = 0; k < 48; k++) a = fmaf(f[k], __ldg(W_map + o*48+k), a);
                y[o] = leaky_f(a);
            }
            float r0 = __ldg(b_efc), r1 = __ldg(b_efc + 1);
            #pragma unroll
            for (int k = 0; k < 8; k++) {
                r0 = fmaf(y[k], __ldg(W_efc + k),     r0);
                r1 = fmaf(y[k], __ldg(W_efc + 8 + k), r1);
            }
            out[b*4 + 0] = r0;
            out[b*4 + 1] = r1;
        }
        return;
    }

    // =======================================================================
    // En blocks: 128 rows (2 batches x 64 neighbors)
    // =======================================================================
    float* At   = sm;              // features (transposed), later h2_T
    float* h1T  = sm + SM_R0;      // h1, then layer3 partial scratch
    float* wbuf = sm + SM_WB;
    float* enb  = sm + SM_EN;
    float* lgb  = sm + SM_LG;

    // ---- phase 0: features, 4 threads per row ----
    {
        int r = tid >> 2;
        int part = tid & 3;
        int b = blk*2 + (r >> 6);
        int n = r & 63;
        int idx2 = (b*64 + n) * 2;
        float* Acol = At + r;
        if (part < 2) {
            float pex = Pego[b*2], pey = Pego[b*2+1];
            float pnx = Pn[idx2],  pny = Pn[idx2+1];
            float dx = pnx - pex,  dy = pny - pey;
            if (part == 0) {
                Acol[0*RS] = pex;  Acol[1*RS] = pey;
                Acol[2*RS] = pnx;  Acol[3*RS] = pny;
                Acol[4*RS] = dx;   Acol[5*RS] = dy;
                Acol[112*RS] = Cn[idx2];
                Acol[113*RS] = Cn[idx2+1];
                aug_poly(Acol, 6, dx, dy);
                aug_sin(Acol, 6, dx, dy, W_s1, b_s1, 0, 9);
            } else {
                aug_sin(Acol, 6, dx, dy, W_s1, b_s1, 9, 17);
            }
        } else {
            float vex = Vego[b*2], vey = Vego[b*2+1];
            float vnx = Vn[idx2],  vny = Vn[idx2+1];
            float dx = vnx - vex,  dy = vny - vey;
            if (part == 2) {
                Acol[56*RS] = vex;  Acol[57*RS] = vey;
                Acol[58*RS] = vnx;  Acol[59*RS] = vny;
                Acol[60*RS] = dx;   Acol[61*RS] = dy;
                aug_poly(Acol, 62, dx, dy);
                aug_sin(Acol, 62, dx, dy, W_s1, b_s1, 0, 9);
            } else {
                aug_sin(Acol, 62, dx, dy, W_s1, b_s1, 9, 17);
            }
        }
        // zero pad rows 114..119 (weights there are zero; avoid NaN*0)
        for (int idx = tid; idx < 6*128; idx += 512)
            At[(114 + (idx >> 7))*RS + (idx & 127)] = 0.f;
    }
    __syncthreads();

    int rt = tid & 31;     // 32 row-groups (4 rows each)
    int ot = tid >> 5;     // 16 out-groups

    // ---- layer1: [128,114(+6 pad)] -> [128,256], leaky ----
    gemm_staged<120, 16, 8, 256>(At, g_W1c, b1, h1T, wbuf, rt, ot, tid);
    __syncthreads();

    // ---- layer2: [128,256] -> [128,128], leaky ----
    gemm_staged<256, 8, 16, 128>(h1T, g_W2c, b2, At, wbuf, rt, ot, tid);
    __syncthreads();

    // ---- layer3: all 512 threads (4 k-segments x 128 rows) ----
    {
        int seg = tid >> 7;
        int r   = tid & 127;
        int k0  = seg * 32;
        float a0 = 0.f, a1 = 0.f;
        #pragma unroll 8
        for (int k = k0; k < k0 + 32; k++) {
            float h = At[k*RS + r];
            a0 = fmaf(h, __ldg(W3 + k),       a0);
            a1 = fmaf(h, __ldg(W3 + 128 + k), a1);
        }
        h1T[(seg*128 + r)*2]     = a0;
        h1T[(seg*128 + r)*2 + 1] = a1;
    }
    __syncthreads();

    // ---- layer3 reduce + logits ----
    if (tid < 128) {
        int r = tid;
        float a0 = __ldg(b3), a1 = __ldg(b3 + 1);
        #pragma unroll
        for (int seg = 0; seg < 4; seg++) {
            a0 += h1T[(seg*128 + r)*2];
            a1 += h1T[(seg*128 + r)*2 + 1];
        }
        enb[r*2]   = a0;
        enb[r*2+1] = a1;
        int b = blk*2 + (r >> 6);
        int n = r & 63;
        int idx2 = (b*64 + n) * 2;
        float pnx = Pn[idx2], pny = Pn[idx2+1];
        float dx = pnx - Pego[b*2], dy = pny - Pego[b*2+1];
        float lg = __ldg(bw);
        lg = fmaf(__ldg(Ww+0), a0,  lg);
        lg = fmaf(__ldg(Ww+1), a1,  lg);
        lg = fmaf(__ldg(Ww+2), pnx, lg);
        lg = fmaf(__ldg(Ww+3), pny, lg);
        lg = fmaf(__ldg(Ww+4), dx,  lg);
        lg = fmaf(__ldg(Ww+5), dy,  lg);
        lgb[r] = lg;
    }
    __syncthreads();

    // ---- softmax over 64 neighbors + weighted sum ----
    if (tid < 64) {
        int w = tid >> 5, l = tid & 31;
        int base = w * 64;
        float v0 = lgb[base + l], v1 = lgb[base + 32 + l];
        float m = fmaxf(v0, v1);
        #pragma unroll
        for (int off = 16; off; off >>= 1)
            m = fmaxf(m, __shfl_xor_sync(0xffffffffu, m, off));
        float e0 = expf(v0 - m), e1 = expf(v1 - m);
        float s  = e0 + e1;
        float n0 = e0 * enb[(base+l)*2]     + e1 * enb[(base+32+l)*2];
        float n1 = e0 * enb[(base+l)*2 + 1] + e1 * enb[(base+32+l)*2 + 1];
        #pragma unroll
        for (int off = 16; off; off >>= 1) {
            s  += __shfl_xor_sync(0xffffffffu, s,  off);
            n0 += __shfl_xor_sync(0xffffffffu, n0, off);
            n1 += __shfl_xor_sync(0xffffffffu, n1, off);
        }
        if (l == 0) {
            int b = blk*2 + w;
            out[b*4 + 2] = n0 / s;
            out[b*4 + 3] = n1 / s;
        }
    }
}

// ---------------------------------------------------------------------------
extern "C" void kernel_launch(void* const* d_in, const int* in_sizes, int n_in,
                              void* d_out, int out_size)
{
    const float* ego_y = (const float*)d_in[0];
    const float* Pn    = (const float*)d_in[1];
    const float* Pego  = (const float*)d_in[2];
    const float* Vn    = (const float*)d_in[3];
    const float* Vego  = (const float*)d_in[4];
    const float* Cn    = (const float*)d_in[5];
    const float* W_sel = (const float*)d_in[6];
    const float* b_sel = (const float*)d_in[7];
    const float* W_s0  = (const float*)d_in[8];
    const float* b_s0  = (const float*)d_in[9];
    const float* W_map = (const float*)d_in[10];
    const float* b_map = (const float*)d_in[11];
    const float* W_efc = (const float*)d_in[12];
    const float* b_efc = (const float*)d_in[13];
    const float* W_s1  = (const float*)d_in[14];
    const float* b_s1  = (const float*)d_in[15];
    const float* W1    = (const float*)d_in[16];
    const float* b1    = (const float*)d_in[17];
    const float* W2    = (const float*)d_in[18];
    const float* b2    = (const float*)d_in[19];
    const float* W3    = (const float*)d_in[20];
    const float* b3    = (const float*)d_in[21];
    const float* Ww    = (const float*)d_in[22];
    const float* bw    = (const float*)d_in[23];
    float* out = (float*)d_out;

    size_t smem_bytes = (size_t)SM_TOT * sizeof(float);
    cudaFuncSetAttribute(fused_kernel, cudaFuncAttributeMaxDynamicSharedMemorySize,
                         (int)smem_bytes);

    repack_kernel<<<128, 256>>>(W1, W2);
    fused_kernel<<<EN_BLOCKS + 16, 512, smem_bytes>>>(
        ego_y, Pn, Pego, Vn, Vego, Cn,
        W_sel, b_sel, W_s0, b_s0, W_map, b_map, W_efc, b_efc,
        W_s1, b_s1, b1, b2, W3, b3, Ww, bw, out);
}

// round 8
// speedup vs baseline: 1.4044x; 1.1701x over previous
#include <cuda_runtime.h>
#include <math.h>
#include <stdint.h>

#define EPSF 1e-6f
#define NBATCH 4096
#define RS2 64            // row stride for 64-row tiles

// k-major repacked weights; W1 padded to 116 k-rows (zeros)
__device__ float g_W1c[116 * 256];   // [k][out]
__device__ float g_W2c[256 * 128];   // [k][out]

// ---------------------------------------------------------------------------
__device__ __forceinline__ float2 ffma2(float2 a, float2 b, float2 c) {
    float2 d;
    asm("fma.rn.f32x2 %0, %1, %2, %3;"
        : "=l"(reinterpret_cast<unsigned long long&>(d))
        : "l"(reinterpret_cast<unsigned long long&>(a)),
          "l"(reinterpret_cast<unsigned long long&>(b)),
          "l"(reinterpret_cast<unsigned long long&>(c)));
    return d;
}

__device__ __forceinline__ float my_sinf(float x) {
    float k = rintf(x * 0.318309886183790672f);
    float r = fmaf(k, -3.14159274101257324f, x);
    r = fmaf(k, 8.742278012618954e-8f, r);
    float r2 = r * r;
    float p = -2.50521083854e-08f;
    p = fmaf(p, r2, 2.75573192239e-06f);
    p = fmaf(p, r2, -1.98412698413e-04f);
    p = fmaf(p, r2, 8.33333333333e-03f);
    p = fmaf(p, r2, -1.66666666667e-01f);
    float s = fmaf(p * r2, r, r);
    int ki = __float2int_rn(k);
    return (ki & 1) ? -s : s;
}

__device__ __forceinline__ float leaky_f(float x) { return x >= 0.f ? x : 0.1f * x; }

// ---------------------------------------------------------------------------
__global__ void repack_kernel(const float* __restrict__ W1,
                              const float* __restrict__ W2)
{
    int idx = blockIdx.x * 256 + threadIdx.x;
    if (idx < 116 * 256) {
        int k = idx >> 8, o = idx & 255;
        g_W1c[idx] = (k < 114) ? W1[o * 114 + k] : 0.f;
    }
    if (idx < 256 * 128) {
        int k = idx >> 7, o = idx & 127;
        g_W2c[idx] = W2[o * 256 + k];
    }
}

// ---------------------------------------------------------------------------
// feature helpers (stride RS2)
// ---------------------------------------------------------------------------
__device__ __forceinline__ void aug_poly(float* __restrict__ Acol, int base,
                                         float dx, float dy)
{
    Acol[(base+0)*RS2] = dx;
    Acol[(base+1)*RS2] = dy;
    float sqx = dx*dx + EPSF, sqy = dy*dy + EPSF;
    float cbx = dx*dx*dx + EPSF, cby = dy*dy*dy + EPSF;
    float exx = expf(dx) + EPSF, exy = expf(dy) + EPSF;
    Acol[(base+19)*RS2] = sqx;  Acol[(base+20)*RS2] = sqy;
    Acol[(base+21)*RS2] = cbx;  Acol[(base+22)*RS2] = cby;
    Acol[(base+23)*RS2] = exx;  Acol[(base+24)*RS2] = exy;
    Acol[(base+25)*RS2] = 1.0f / (dx + EPSF);
    Acol[(base+26)*RS2] = 1.0f / (dy + EPSF);
    Acol[(base+44)*RS2] = 1.0f / sqx;  Acol[(base+45)*RS2] = 1.0f / sqy;
    Acol[(base+46)*RS2] = 1.0f / cbx;  Acol[(base+47)*RS2] = 1.0f / cby;
    Acol[(base+48)*RS2] = 1.0f / exx;  Acol[(base+49)*RS2] = 1.0f / exy;
}

__device__ __forceinline__ void aug_sin(float* __restrict__ Acol, int base,
                                        float dx, float dy,
                                        const float* __restrict__ W_s1,
                                        const float* __restrict__ b_s1,
                                        int j0, int j1)
{
    #pragma unroll 1
    for (int j = j0; j < j1; j++) {
        float arg = fmaf(dx, __ldg(W_s1 + 2*j),
                    fmaf(dy, __ldg(W_s1 + 2*j + 1), __ldg(b_s1 + j)));
        float s = my_sinf(arg) + EPSF;
        Acol[(base+2+j)*RS2]  = s;
        Acol[(base+27+j)*RS2] = 1.0f / s;
    }
}

// ---------------------------------------------------------------------------
// Staged GEMM (64-row tile, 256 threads): weights double-buffered in smem,
// chunk = 1024 floats (CH k-rows). rt = tid&15 owns rows 4rt..4rt+3
// (1 LDS.128/k); ot = tid>>4 owns outs ot*TO..+TO-1 (broadcast LDS).
// ---------------------------------------------------------------------------
template<int KP, int TO, int CH, int LDWC>
__device__ __forceinline__ void gemm_staged(const float* __restrict__ At,
                                            const float* __restrict__ Wg,
                                            const float* __restrict__ bg,
                                            float* __restrict__ Ct,
                                            float* __restrict__ wbuf,
                                            int rt, int ot, int tid)
{
    constexpr int NC  = KP / CH;
    constexpr int CHW = CH * LDWC;          // 1024 floats per chunk
    float2 acc[2][TO];
    #pragma unroll
    for (int i = 0; i < TO; i++) {
        float bo = __ldg(bg + ot*TO + i);
        acc[0][i] = make_float2(bo, bo);
        acc[1][i] = make_float2(bo, bo);
    }

    // stage chunk 0 (1 float4 per thread)
    {
        float4 st = __ldg(reinterpret_cast<const float4*>(Wg) + tid);
        *(reinterpret_cast<float4*>(wbuf) + tid) = st;
    }
    __syncthreads();

    #pragma unroll 1
    for (int c = 0; c < NC; c++) {
        int cn = (c + 1 < NC) ? c + 1 : c;
        float4 nx = __ldg(reinterpret_cast<const float4*>(Wg + cn*CHW) + tid);

        const float* wb = wbuf + (c & 1)*CHW + ot*TO;
        const float* xk = At + (c*CH)*RS2 + 4*rt;

        #pragma unroll
        for (int k = 0; k < CH; k++) {
            float4 xv = *reinterpret_cast<const float4*>(xk + k*RS2);
            float w[TO];
            #pragma unroll
            for (int i = 0; i < TO/4; i++) {
                float4 t = *reinterpret_cast<const float4*>(wb + k*LDWC + 4*i);
                w[4*i+0] = t.x; w[4*i+1] = t.y; w[4*i+2] = t.z; w[4*i+3] = t.w;
            }
            float2 p0 = make_float2(xv.x, xv.y);
            float2 p1 = make_float2(xv.z, xv.w);
            #pragma unroll
            for (int i = 0; i < TO; i++) {
                float2 ws = make_float2(w[i], w[i]);
                acc[0][i] = ffma2(p0, ws, acc[0][i]);
                acc[1][i] = ffma2(p1, ws, acc[1][i]);
            }
        }

        *(reinterpret_cast<float4*>(wbuf + ((c + 1) & 1)*CHW) + tid) = nx;
        __syncthreads();
    }

    // epilogue: leaky + 1 STS.128 per out
    #pragma unroll
    for (int i = 0; i < TO; i++) {
        float4 v;
        v.x = leaky_f(acc[0][i].x);
        v.y = leaky_f(acc[0][i].y);
        v.z = leaky_f(acc[1][i].x);
        v.w = leaky_f(acc[1][i].y);
        *reinterpret_cast<float4*>(Ct + (ot*TO + i)*RS2 + 4*rt) = v;
    }
}

// smem layout (floats): region A (At features 116x64, later h2T 128x64),
// h1T 256x64, wbuf 2x1024, enb 128, lgb 64
#define SM_A    0
#define SM_H1   8192
#define SM_WB   (SM_H1 + 16384)
#define SM_EN   (SM_WB + 2048)
#define SM_LG   (SM_EN + 128)
#define SM_TOT  (SM_LG + 64)

#define EN_BLOCKS NBATCH

__global__ void __launch_bounds__(256, 2)
fused_kernel(const float* __restrict__ ego_y,
             const float* __restrict__ Pn,  const float* __restrict__ Pego,
             const float* __restrict__ Vn,  const float* __restrict__ Vego,
             const float* __restrict__ Cn,
             const float* __restrict__ W_sel, const float* __restrict__ b_sel,
             const float* __restrict__ W_s0,  const float* __restrict__ b_s0,
             const float* __restrict__ W_map, const float* __restrict__ b_map,
             const float* __restrict__ W_efc, const float* __restrict__ b_efc,
             const float* __restrict__ W_s1, const float* __restrict__ b_s1,
             const float* __restrict__ b1,
             const float* __restrict__ b2,
             const float* __restrict__ W3,  const float* __restrict__ b3,
             const float* __restrict__ Ww,  const float* __restrict__ bw,
             float* __restrict__ out)
{
    extern __shared__ float sm[];
    int tid = threadIdx.x;
    int blk = blockIdx.x;

    // =======================================================================
    // Er head blocks
    // =======================================================================
    if (blk >= EN_BLOCKS) {
        {
            int b = (blk - EN_BLOCKS) * 256 + tid;
            float ey = ego_y[b];
            float dy[4] = { 13.55f - ey, 17.45f - ey, 21.12f - ey, 24.91f - ey };

            float z[4];
            #pragma unroll
            for (int o = 0; o < 4; o++) {
                float a = __ldg(b_sel + o);
                #pragma unroll
                for (int i = 0; i < 4; i++) a = fmaf(dy[i], __ldg(W_sel + o*4+i), a);
                z[o] = a;
            }
            float m = fmaxf(fmaxf(z[0], z[1]), fmaxf(z[2], z[3]));
            float e[4], ssum = 0.f;
            #pragma unroll
            for (int i = 0; i < 4; i++) { e[i] = expf(z[i] - m); ssum += e[i]; }
            float x[4];
            #pragma unroll
            for (int i = 0; i < 4; i++) x[i] = (e[i] / ssum) * dy[i];

            float f[48];
            #pragma unroll
            for (int i = 0; i < 4; i++) f[i] = x[i];
            #pragma unroll
            for (int j = 0; j < 8; j++) {
                float arg = __ldg(b_s0 + j);
                #pragma unroll
                for (int i = 0; i < 4; i++) arg = fmaf(x[i], __ldg(W_s0 + j*4+i), arg);
                float s = my_sinf(arg) + EPSF;
                f[4 + j] = s;
                f[28 + j] = 1.0f / s;
            }
            #pragma unroll
            for (int i = 0; i < 4; i++) {
                float sq = x[i]*x[i] + EPSF;
                float cb = x[i]*x[i]*x[i] + EPSF;
                float ex = expf(x[i]) + EPSF;
                f[12+i] = sq;           f[36+i] = 1.0f / sq;
                f[16+i] = cb;           f[40+i] = 1.0f / cb;
                f[20+i] = ex;           f[44+i] = 1.0f / ex;
                f[24+i] = 1.0f / (x[i] + EPSF);
            }
            float y[8];
            #pragma unroll
            for (int o = 0; o < 8; o++) {
                float a = __ldg(b_map + o);
                #pragma unroll
                for (int k = 0; k < 48; k++) a = fmaf(f[k], __ldg(W_map + o*48+k), a);
                y[o] = leaky_f(a);
            }
            float r0 = __ldg(b_efc), r1 = __ldg(b_efc + 1);
            #pragma unroll
            for (int k = 0; k < 8; k++) {
                r0 = fmaf(y[k], __ldg(W_efc + k),     r0);
                r1 = fmaf(y[k], __ldg(W_efc + 8 + k), r1);
            }
            out[b*4 + 0] = r0;
            out[b*4 + 1] = r1;
        }
        return;
    }

    // =======================================================================
    // En blocks: 64 rows (1 batch x 64 neighbors)
    // =======================================================================
    float* At   = sm + SM_A;       // features (stride 64), later h2T
    float* h1T  = sm + SM_H1;      // h1, later layer3 partial scratch
    float* wbuf = sm + SM_WB;
    float* enb  = sm + SM_EN;
    float* lgb  = sm + SM_LG;

    // ---- phase 0: features, 4 threads per row ----
    {
        int n = tid >> 2;          // neighbor 0..63
        int part = tid & 3;
        int b = blk;
        int idx2 = (b*64 + n) * 2;
        float* Acol = At + n;
        if (part < 2) {
            float pex = Pego[b*2], pey = Pego[b*2+1];
            float pnx = Pn[idx2],  pny = Pn[idx2+1];
            float dx = pnx - pex,  dy = pny - pey;
            if (part == 0) {
                Acol[0*RS2] = pex;  Acol[1*RS2] = pey;
                Acol[2*RS2] = pnx;  Acol[3*RS2] = pny;
                Acol[4*RS2] = dx;   Acol[5*RS2] = dy;
                Acol[112*RS2] = Cn[idx2];
                Acol[113*RS2] = Cn[idx2+1];
                aug_poly(Acol, 6, dx, dy);
                aug_sin(Acol, 6, dx, dy, W_s1, b_s1, 0, 9);
            } else {
                aug_sin(Acol, 6, dx, dy, W_s1, b_s1, 9, 17);
            }
        } else {
            float vex = Vego[b*2], vey = Vego[b*2+1];
            float vnx = Vn[idx2],  vny = Vn[idx2+1];
            float dx = vnx - vex,  dy = vny - vey;
            if (part == 2) {
                Acol[56*RS2] = vex;  Acol[57*RS2] = vey;
                Acol[58*RS2] = vnx;  Acol[59*RS2] = vny;
                Acol[60*RS2] = dx;   Acol[61*RS2] = dy;
                aug_poly(Acol, 62, dx, dy);
                aug_sin(Acol, 62, dx, dy, W_s1, b_s1, 0, 9);
            } else {
                aug_sin(Acol, 62, dx, dy, W_s1, b_s1, 9, 17);
            }
        }
        // zero pad rows 114, 115
        if (tid < 128)
            At[(114 + (tid >> 6))*RS2 + (tid & 63)] = 0.f;
    }
    __syncthreads();

    int rt = tid & 15;     // 16 row-groups (4 rows each)
    int ot = tid >> 4;     // 16 out-groups

    // ---- layer1: [64,114(+2 pad)] -> [64,256], leaky (TO=16, CH=4) ----
    gemm_staged<116, 16, 4, 256>(At, g_W1c, b1, h1T, wbuf, rt, ot, tid);
    __syncthreads();

    // ---- layer2: [64,256] -> [64,128], leaky (TO=8, CH=8) ----
    gemm_staged<256, 8, 8, 128>(h1T, g_W2c, b2, At, wbuf, rt, ot, tid);
    __syncthreads();

    // ---- layer3: 256 threads (4 k-segments x 64 rows) ----
    {
        int seg = tid >> 6;
        int r   = tid & 63;
        int k0  = seg * 32;
        float a0 = 0.f, a1 = 0.f;
        #pragma unroll 8
        for (int k = k0; k < k0 + 32; k++) {
            float h = At[k*RS2 + r];
            a0 = fmaf(h, __ldg(W3 + k),       a0);
            a1 = fmaf(h, __ldg(W3 + 128 + k), a1);
        }
        h1T[(seg*64 + r)*2]     = a0;
        h1T[(seg*64 + r)*2 + 1] = a1;
    }
    __syncthreads();

    // ---- layer3 reduce + logits ----
    if (tid < 64) {
        int r = tid;
        float a0 = __ldg(b3), a1 = __ldg(b3 + 1);
        #pragma unroll
        for (int seg = 0; seg < 4; seg++) {
            a0 += h1T[(seg*64 + r)*2];
            a1 += h1T[(seg*64 + r)*2 + 1];
        }
        enb[r*2]   = a0;
        enb[r*2+1] = a1;
        int idx2 = (blk*64 + r) * 2;
        float pnx = Pn[idx2], pny = Pn[idx2+1];
        float dx = pnx - Pego[blk*2], dy = pny - Pego[blk*2+1];
        float lg = __ldg(bw);
        lg = fmaf(__ldg(Ww+0), a0,  lg);
        lg = fmaf(__ldg(Ww+1), a1,  lg);
        lg = fmaf(__ldg(Ww+2), pnx, lg);
        lg = fmaf(__ldg(Ww+3), pny, lg);
        lg = fmaf(__ldg(Ww+4), dx,  lg);
        lg = fmaf(__ldg(Ww+5), dy,  lg);
        lgb[r] = lg;
    }
    __syncthreads();

    // ---- softmax over 64 neighbors + weighted sum (warp 0) ----
    if (tid < 32) {
        int l = tid;
        float v0 = lgb[l], v1 = lgb[32 + l];
        float m = fmaxf(v0, v1);
        #pragma unroll
        for (int off = 16; off; off >>= 1)
            m = fmaxf(m, __shfl_xor_sync(0xffffffffu, m, off));
        float e0 = expf(v0 - m), e1 = expf(v1 - m);
        float s  = e0 + e1;
        float n0 = e0 * enb[l*2]     + e1 * enb[(32+l)*2];
        float n1 = e0 * enb[l*2 + 1] + e1 * enb[(32+l)*2 + 1];
        #pragma unroll
        for (int off = 16; off; off >>= 1) {
            s  += __shfl_xor_sync(0xffffffffu, s,  off);
            n0 += __shfl_xor_sync(0xffffffffu, n0, off);
            n1 += __shfl_xor_sync(0xffffffffu, n1, off);
        }
        if (l == 0) {
            out[blk*4 + 2] = n0 / s;
            out[blk*4 + 3] = n1 / s;
        }
    }
}

// ---------------------------------------------------------------------------
extern "C" void kernel_launch(void* const* d_in, const int* in_sizes, int n_in,
                              void* d_out, int out_size)
{
    const float* ego_y = (const float*)d_in[0];
    const float* Pn    = (const float*)d_in[1];
    const float* Pego  = (const float*)d_in[2];
    const float* Vn    = (const float*)d_in[3];
    const float* Vego  = (const float*)d_in[4];
    const float* Cn    = (const float*)d_in[5];
    const float* W_sel = (const float*)d_in[6];
    const float* b_sel = (const float*)d_in[7];
    const float* W_s0  = (const float*)d_in[8];
    const float* b_s0  = (const float*)d_in[9];
    const float* W_map = (const float*)d_in[10];
    const float* b_map = (const float*)d_in[11];
    const float* W_efc = (const float*)d_in[12];
    const float* b_efc = (const float*)d_in[13];
    const float* W_s1  = (const float*)d_in[14];
    const float* b_s1  = (const float*)d_in[15];
    const float* W1    = (const float*)d_in[16];
    const float* b1    = (const float*)d_in[17];
    const float* W2    = (const float*)d_in[18];
    const float* b2    = (const float*)d_in[19];
    const float* W3    = (const float*)d_in[20];
    const float* b3    = (const float*)d_in[21];
    const float* Ww    = (const float*)d_in[22];
    const float* bw    = (const float*)d_in[23];
    float* out = (float*)d_out;

    size_t smem_bytes = (size_t)SM_TOT * sizeof(float);
    cudaFuncSetAttribute(fused_kernel, cudaFuncAttributeMaxDynamicSharedMemorySize,
                         (int)smem_bytes);

    repack_kernel<<<128, 256>>>(W1, W2);
    fused_kernel<<<EN_BLOCKS + 16, 256, smem_bytes>>>(
        ego_y, Pn, Pego, Vn, Vego, Cn,
        W_sel, b_sel, W_s0, b_s0, W_map, b_map, W_efc, b_efc,
        W_s1, b_s1, b1, b2, W3, b3, Ww, bw, out);
}